// round 13
// baseline (speedup 1.0000x reference)
#include <cuda_runtime.h>
#include <cuda_bf16.h>

#define LATENT   16
#define NREP     10
#define NSTEPS   10
#define NLIB     169
#define DT_F     0.01f
#define CWORDS   (NREP * NLIB * 4)   // 6760 u64 = 54,080 B (< 64 KB constant limit)

#define SEL_LO 0x1010u   // duplicate low bf16 half
#define SEL_HI 0x3232u   // duplicate high bf16 half

__constant__ unsigned long long gC[CWORDS];       // masked bf16x2 coefficient table
__device__   unsigned long long gScratch[CWORDS]; // staging (written by prep kernel)

__device__ __forceinline__ unsigned long long pack2u(unsigned lo, unsigned hi) {
    unsigned long long r;
    asm("mov.b64 %0, {%1, %2};" : "=l"(r) : "r"(lo), "r"(hi));
    return r;
}
__device__ __forceinline__ unsigned hfma2(unsigned a, unsigned b, unsigned c) {
    unsigned d;
    asm("fma.rn.bf16x2 %0, %1, %2, %3;" : "=r"(d) : "r"(a), "r"(b), "r"(c));
    return d;
}
__device__ __forceinline__ unsigned hmul2(unsigned a, unsigned b) {
    unsigned d;
    asm("mul.rn.bf16x2 %0, %1, %2;" : "=r"(d) : "r"(a), "r"(b));
    return d;
}
__device__ __forceinline__ unsigned prmt(unsigned a, unsigned sel) {
    unsigned d;
    asm("prmt.b32 %0, %1, %1, %2;" : "=r"(d) : "r"(a), "r"(sel));
    return d;
}
#define CVT2(dst, lo, hi) \
    asm("cvt.rn.bf16x2.f32 %0, %1, %2;" : "=r"(dst) : "f"(hi), "f"(lo))

__device__ __forceinline__ float bf16lo_f(unsigned v) { return __uint_as_float(v << 16); }
__device__ __forceinline__ float bf16hi_f(unsigned v) { return __uint_as_float(v & 0xFFFF0000u); }

// Prep: masked coefficients -> bf16x2-packed u64 table in device scratch.
__global__ void sindy_prep_kernel(const float* __restrict__ coeff,
                                  const float* __restrict__ mask)
{
    int idx = blockIdx.x * blockDim.x + threadIdx.x;
    if (idx >= CWORDS) return;
    int base = idx * 4;
    float c0 = coeff[base + 0] * mask[base + 0];
    float c1 = coeff[base + 1] * mask[base + 1];
    float c2 = coeff[base + 2] * mask[base + 2];
    float c3 = coeff[base + 3] * mask[base + 3];
    unsigned plo, phi;
    CVT2(plo, c0, c1);
    CVT2(phi, c2, c3);
    gScratch[idx] = pack2u(plo, phi);
}

// Main: identical instruction stream to the 477us (128,4) winner EXCEPT the
// coefficient reads come from __constant__ (LDC, constant port) instead of
// shared (LDS, L1 crossbar). Removes all 676 LDS/warp-step latency chains,
// the smem prologue, and the __syncthreads().
__global__ __launch_bounds__(128, 4)
void sindy_shred_kernel(const float* __restrict__ h_t,
                        float* __restrict__ out,
                        int n_total)
{
    const int r = blockIdx.y;
    const int rb = r * (NLIB * 4);

    const int n0 = blockIdx.x * 384 + threadIdx.x;   // 3 samples/thread
    const int n1 = n0 + 128;
    const int n2 = n0 + 256;
    const bool v1 = (n1 < n_total);
    const bool v2 = (n2 < n_total);
    if (n0 >= n_total) return;

    float z0[LATENT], z1[LATENT], z2[LATENT];
    {
        const float4* p0 = reinterpret_cast<const float4*>(h_t + (size_t)n0 * LATENT);
        #pragma unroll
        for (int k = 0; k < 4; k++) {
            float4 v = p0[k];
            z0[4*k+0] = v.x; z0[4*k+1] = v.y; z0[4*k+2] = v.z; z0[4*k+3] = v.w;
        }
        if (v1) {
            const float4* p1 = reinterpret_cast<const float4*>(h_t + (size_t)n1 * LATENT);
            #pragma unroll
            for (int k = 0; k < 4; k++) {
                float4 v = p1[k];
                z1[4*k+0] = v.x; z1[4*k+1] = v.y; z1[4*k+2] = v.z; z1[4*k+3] = v.w;
            }
        } else {
            #pragma unroll
            for (int k = 0; k < LATENT; k++) z1[k] = 0.0f;
        }
        if (v2) {
            const float4* p2 = reinterpret_cast<const float4*>(h_t + (size_t)n2 * LATENT);
            #pragma unroll
            for (int k = 0; k < 4; k++) {
                float4 v = p2[k];
                z2[4*k+0] = v.x; z2[4*k+1] = v.y; z2[4*k+2] = v.z; z2[4*k+3] = v.w;
            }
        } else {
            #pragma unroll
            for (int k = 0; k < LATENT; k++) z2[k] = 0.0f;
        }
    }

    for (int step = 0; step < NSTEPS; step++) {
        unsigned zp0[8], zp1[8], zp2[8];
        #pragma unroll
        for (int m = 0; m < 8; m++) {
            CVT2(zp0[m], z0[2*m], z0[2*m+1]);
            CVT2(zp1[m], z1[2*m], z1[2*m+1]);
            CVT2(zp2[m], z2[2*m], z2[2*m+1]);
        }

        unsigned acc0[8], acc1[8], acc2[8];
        #pragma unroll
        for (int m = 0; m < 4; m++) {
            unsigned long long c = gC[rb + m];    // const-space load
            unsigned clo = (unsigned)c, chi = (unsigned)(c >> 32);
            acc0[2*m] = clo; acc0[2*m+1] = chi;
            acc1[2*m] = clo; acc1[2*m+1] = chi;
            acc2[2*m] = clo; acc2[2*m+1] = chi;
        }

        // Pure contraction row: 4x LDC.64 + 24x HFMA2
        #define ROW_OP(l, t0, t1, t2) do {                                     \
            _Pragma("unroll")                                                  \
            for (int m = 0; m < 4; m++) {                                      \
                unsigned long long cc = gC[rb + (l) * 4 + m];                  \
                unsigned clo = (unsigned)cc, chi = (unsigned)(cc >> 32);       \
                acc0[2*m]   = hfma2((t0), clo, acc0[2*m]);                     \
                acc0[2*m+1] = hfma2((t0), chi, acc0[2*m+1]);                   \
                acc1[2*m]   = hfma2((t1), clo, acc1[2*m]);                     \
                acc1[2*m+1] = hfma2((t1), chi, acc1[2*m+1]);                   \
                acc2[2*m]   = hfma2((t2), clo, acc2[2*m]);                     \
                acc2[2*m+1] = hfma2((t2), chi, acc2[2*m+1]);                   \
            }                                                                  \
        } while (0)

        // Linear rows 1..16
        {
            int l = 1;
            #pragma unroll 2
            for (int m = 0; m < 8; m++) {
                unsigned t0 = prmt(zp0[m], SEL_LO);
                unsigned t1 = prmt(zp1[m], SEL_LO);
                unsigned t2 = prmt(zp2[m], SEL_LO);
                ROW_OP(l, t0, t1, t2); l++;
                t0 = prmt(zp0[m], SEL_HI);
                t1 = prmt(zp1[m], SEL_HI);
                t2 = prmt(zp2[m], SEL_HI);
                ROW_OP(l, t0, t1, t2); l++;
            }
        }

        // Quadratic rows 17..152
        {
            int l = 1 + LATENT;
            for (int i = 0; i < LATENT; i++) {
                unsigned sel = (i & 1) ? SEL_HI : SEL_LO;
                unsigned zi0 = prmt(zp0[i >> 1], sel);
                unsigned zi1 = prmt(zp1[i >> 1], sel);
                unsigned zi2 = prmt(zp2[i >> 1], sel);
                int m = i >> 1;
                {
                    unsigned pp0 = hmul2(zi0, zp0[m]);
                    unsigned pp1 = hmul2(zi1, zp1[m]);
                    unsigned pp2 = hmul2(zi2, zp2[m]);
                    if (!(i & 1)) {
                        ROW_OP(l, prmt(pp0, SEL_LO), prmt(pp1, SEL_LO), prmt(pp2, SEL_LO));
                        l++;
                    }
                    ROW_OP(l, prmt(pp0, SEL_HI), prmt(pp1, SEL_HI), prmt(pp2, SEL_HI));
                    l++;
                }
                for (m = (i >> 1) + 1; m < 8; m++) {
                    unsigned pp0 = hmul2(zi0, zp0[m]);
                    unsigned pp1 = hmul2(zi1, zp1[m]);
                    unsigned pp2 = hmul2(zi2, zp2[m]);
                    ROW_OP(l, prmt(pp0, SEL_LO), prmt(pp1, SEL_LO), prmt(pp2, SEL_LO));
                    l++;
                    ROW_OP(l, prmt(pp0, SEL_HI), prmt(pp1, SEL_HI), prmt(pp2, SEL_HI));
                    l++;
                }
            }
        }

        // Sine rows 153..168 (inline)
        {
            int l = 153;
            #pragma unroll 2
            for (int m = 0; m < 8; m++) {
                unsigned s0, s1, s2;
                CVT2(s0, __sinf(z0[2*m]), __sinf(z0[2*m+1]));
                CVT2(s1, __sinf(z1[2*m]), __sinf(z1[2*m+1]));
                CVT2(s2, __sinf(z2[2*m]), __sinf(z2[2*m+1]));
                ROW_OP(l, prmt(s0, SEL_LO), prmt(s1, SEL_LO), prmt(s2, SEL_LO));
                l++;
                ROW_OP(l, prmt(s0, SEL_HI), prmt(s1, SEL_HI), prmt(s2, SEL_HI));
                l++;
            }
        }
        #undef ROW_OP

        // Euler: z += dz * DT
        #pragma unroll
        for (int q = 0; q < 8; q++) {
            z0[2*q+0] = fmaf(bf16lo_f(acc0[q]), DT_F, z0[2*q+0]);
            z0[2*q+1] = fmaf(bf16hi_f(acc0[q]), DT_F, z0[2*q+1]);
            z1[2*q+0] = fmaf(bf16lo_f(acc1[q]), DT_F, z1[2*q+0]);
            z1[2*q+1] = fmaf(bf16hi_f(acc1[q]), DT_F, z1[2*q+1]);
            z2[2*q+0] = fmaf(bf16lo_f(acc2[q]), DT_F, z2[2*q+0]);
            z2[2*q+1] = fmaf(bf16hi_f(acc2[q]), DT_F, z2[2*q+1]);
        }
    }

    {
        float4* po = reinterpret_cast<float4*>(out + ((size_t)n0 * NREP + r) * LATENT);
        #pragma unroll
        for (int k = 0; k < 4; k++)
            po[k] = make_float4(z0[4*k+0], z0[4*k+1], z0[4*k+2], z0[4*k+3]);
        if (v1) {
            float4* p1 = reinterpret_cast<float4*>(out + ((size_t)n1 * NREP + r) * LATENT);
            #pragma unroll
            for (int k = 0; k < 4; k++)
                p1[k] = make_float4(z1[4*k+0], z1[4*k+1], z1[4*k+2], z1[4*k+3]);
        }
        if (v2) {
            float4* p2 = reinterpret_cast<float4*>(out + ((size_t)n2 * NREP + r) * LATENT);
            #pragma unroll
            for (int k = 0; k < 4; k++)
                p2[k] = make_float4(z2[4*k+0], z2[4*k+1], z2[4*k+2], z2[4*k+3]);
        }
    }
}

extern "C" void kernel_launch(void* const* d_in, const int* in_sizes, int n_in,
                              void* d_out, int out_size)
{
    const float* h_t   = (const float*)d_in[0];   // [50000, 16]
    const float* coeff = (const float*)d_in[1];   // [10, 169, 16]
    const float* mask  = (const float*)d_in[2];   // [10, 169, 16]
    float* out = (float*)d_out;                   // [50000, 10, 16]

    int n_total = in_sizes[0] / LATENT;

    // 1) build masked bf16 table in device scratch
    sindy_prep_kernel<<<(CWORDS + 255) / 256, 256>>>(coeff, mask);

    // 2) publish to __constant__ (device-to-device async copy; graph-capturable)
    void* scratch_ptr = nullptr;
    cudaGetSymbolAddress(&scratch_ptr, gScratch);
    cudaMemcpyToSymbolAsync(gC, scratch_ptr, sizeof(unsigned long long) * CWORDS,
                            0, cudaMemcpyDeviceToDevice);

    // 3) main kernel
    int blocks_x = (n_total + 383) / 384;
    dim3 grid((unsigned)blocks_x, NREP, 1);
    sindy_shred_kernel<<<grid, 128>>>(h_t, out, n_total);
}

// round 14
// speedup vs baseline: 1.2949x; 1.2949x over previous
#include <cuda_runtime.h>
#include <cuda_bf16.h>

#define LATENT   16
#define NREP     10
#define NSTEPS   10
#define NLIB     169
#define DT_F     0.01f

#define SEL_LO 0x1010u   // duplicate low bf16 half
#define SEL_HI 0x3232u   // duplicate high bf16 half

__device__ __forceinline__ unsigned hfma2(unsigned a, unsigned b, unsigned c) {
    unsigned d;
    asm("fma.rn.bf16x2 %0, %1, %2, %3;" : "=r"(d) : "r"(a), "r"(b), "r"(c));
    return d;
}
__device__ __forceinline__ unsigned hmul2(unsigned a, unsigned b) {
    unsigned d;
    asm("mul.rn.bf16x2 %0, %1, %2;" : "=r"(d) : "r"(a), "r"(b));
    return d;
}
__device__ __forceinline__ unsigned prmt(unsigned a, unsigned sel) {
    unsigned d;
    asm("prmt.b32 %0, %1, %1, %2;" : "=r"(d) : "r"(a), "r"(sel));
    return d;
}
#define CVT2(dst, lo, hi) \
    asm("cvt.rn.bf16x2.f32 %0, %1, %2;" : "=r"(dst) : "f"(hi), "f"(lo))

__device__ __forceinline__ float bf16lo_f(unsigned v) { return __uint_as_float(v << 16); }
__device__ __forceinline__ float bf16hi_f(unsigned v) { return __uint_as_float(v & 0xFFFF0000u); }

// The 477us (128,4) winner with ONE change: coefficient rows are read from
// shared as 2x LDS.128 (uint4) instead of 4x LDS.64 — halves LDS instruction
// count. Safe now (unlike the fp32 R3 attempt) because accumulators are
// scalar u32: the only 4-aligned quads are short-lived load temps.
__global__ __launch_bounds__(128, 4)
void sindy_shred_kernel(const float* __restrict__ h_t,
                        const float* __restrict__ coeff,
                        const float* __restrict__ mask,
                        float* __restrict__ out,
                        int n_total)
{
    // C4[row*2 + h] = uint4 with coeffs d=8h..8h+7 as four bf16x2 pairs
    __shared__ __align__(16) uint4 C4[NLIB * 2];

    const int r = blockIdx.y;
    {
        const float* cr = coeff + (size_t)r * NLIB * LATENT;
        const float* mr = mask  + (size_t)r * NLIB * LATENT;
        for (int idx = threadIdx.x; idx < NLIB * 2; idx += blockDim.x) {
            int base = idx * 8;
            uint4 q;
            {
                float c0 = cr[base+0]*mr[base+0], c1 = cr[base+1]*mr[base+1];
                CVT2(q.x, c0, c1);
            }
            {
                float c0 = cr[base+2]*mr[base+2], c1 = cr[base+3]*mr[base+3];
                CVT2(q.y, c0, c1);
            }
            {
                float c0 = cr[base+4]*mr[base+4], c1 = cr[base+5]*mr[base+5];
                CVT2(q.z, c0, c1);
            }
            {
                float c0 = cr[base+6]*mr[base+6], c1 = cr[base+7]*mr[base+7];
                CVT2(q.w, c0, c1);
            }
            C4[idx] = q;
        }
    }
    __syncthreads();

    const int n0 = blockIdx.x * 384 + threadIdx.x;   // 3 samples/thread
    const int n1 = n0 + 128;
    const int n2 = n0 + 256;
    const bool v1 = (n1 < n_total);
    const bool v2 = (n2 < n_total);
    if (n0 >= n_total) return;

    float z0[LATENT], z1[LATENT], z2[LATENT];
    {
        const float4* p0 = reinterpret_cast<const float4*>(h_t + (size_t)n0 * LATENT);
        #pragma unroll
        for (int k = 0; k < 4; k++) {
            float4 v = p0[k];
            z0[4*k+0] = v.x; z0[4*k+1] = v.y; z0[4*k+2] = v.z; z0[4*k+3] = v.w;
        }
        if (v1) {
            const float4* p1 = reinterpret_cast<const float4*>(h_t + (size_t)n1 * LATENT);
            #pragma unroll
            for (int k = 0; k < 4; k++) {
                float4 v = p1[k];
                z1[4*k+0] = v.x; z1[4*k+1] = v.y; z1[4*k+2] = v.z; z1[4*k+3] = v.w;
            }
        } else {
            #pragma unroll
            for (int k = 0; k < LATENT; k++) z1[k] = 0.0f;
        }
        if (v2) {
            const float4* p2 = reinterpret_cast<const float4*>(h_t + (size_t)n2 * LATENT);
            #pragma unroll
            for (int k = 0; k < 4; k++) {
                float4 v = p2[k];
                z2[4*k+0] = v.x; z2[4*k+1] = v.y; z2[4*k+2] = v.z; z2[4*k+3] = v.w;
            }
        } else {
            #pragma unroll
            for (int k = 0; k < LATENT; k++) z2[k] = 0.0f;
        }
    }

    for (int step = 0; step < NSTEPS; step++) {
        unsigned zp0[8], zp1[8], zp2[8];
        #pragma unroll
        for (int m = 0; m < 8; m++) {
            CVT2(zp0[m], z0[2*m], z0[2*m+1]);
            CVT2(zp1[m], z1[2*m], z1[2*m+1]);
            CVT2(zp2[m], z2[2*m], z2[2*m+1]);
        }

        unsigned acc0[8], acc1[8], acc2[8];
        {
            uint4 qa = C4[0], qb = C4[1];
            acc0[0]=qa.x; acc0[1]=qa.y; acc0[2]=qa.z; acc0[3]=qa.w;
            acc0[4]=qb.x; acc0[5]=qb.y; acc0[6]=qb.z; acc0[7]=qb.w;
            acc1[0]=qa.x; acc1[1]=qa.y; acc1[2]=qa.z; acc1[3]=qa.w;
            acc1[4]=qb.x; acc1[5]=qb.y; acc1[6]=qb.z; acc1[7]=qb.w;
            acc2[0]=qa.x; acc2[1]=qa.y; acc2[2]=qa.z; acc2[3]=qa.w;
            acc2[4]=qb.x; acc2[5]=qb.y; acc2[6]=qb.z; acc2[7]=qb.w;
        }

        // Contraction row: 2x LDS.128 + 24x HFMA2
        #define ROW_OP(l, t0, t1, t2) do {                                     \
            uint4 qa_ = C4[(l) * 2];                                           \
            uint4 qb_ = C4[(l) * 2 + 1];                                       \
            acc0[0] = hfma2((t0), qa_.x, acc0[0]);                             \
            acc0[1] = hfma2((t0), qa_.y, acc0[1]);                             \
            acc0[2] = hfma2((t0), qa_.z, acc0[2]);                             \
            acc0[3] = hfma2((t0), qa_.w, acc0[3]);                             \
            acc0[4] = hfma2((t0), qb_.x, acc0[4]);                             \
            acc0[5] = hfma2((t0), qb_.y, acc0[5]);                             \
            acc0[6] = hfma2((t0), qb_.z, acc0[6]);                             \
            acc0[7] = hfma2((t0), qb_.w, acc0[7]);                             \
            acc1[0] = hfma2((t1), qa_.x, acc1[0]);                             \
            acc1[1] = hfma2((t1), qa_.y, acc1[1]);                             \
            acc1[2] = hfma2((t1), qa_.z, acc1[2]);                             \
            acc1[3] = hfma2((t1), qa_.w, acc1[3]);                             \
            acc1[4] = hfma2((t1), qb_.x, acc1[4]);                             \
            acc1[5] = hfma2((t1), qb_.y, acc1[5]);                             \
            acc1[6] = hfma2((t1), qb_.z, acc1[6]);                             \
            acc1[7] = hfma2((t1), qb_.w, acc1[7]);                             \
            acc2[0] = hfma2((t2), qa_.x, acc2[0]);                             \
            acc2[1] = hfma2((t2), qa_.y, acc2[1]);                             \
            acc2[2] = hfma2((t2), qa_.z, acc2[2]);                             \
            acc2[3] = hfma2((t2), qa_.w, acc2[3]);                             \
            acc2[4] = hfma2((t2), qb_.x, acc2[4]);                             \
            acc2[5] = hfma2((t2), qb_.y, acc2[5]);                             \
            acc2[6] = hfma2((t2), qb_.z, acc2[6]);                             \
            acc2[7] = hfma2((t2), qb_.w, acc2[7]);                             \
        } while (0)

        // Linear rows 1..16
        {
            int l = 1;
            #pragma unroll 2
            for (int m = 0; m < 8; m++) {
                unsigned t0 = prmt(zp0[m], SEL_LO);
                unsigned t1 = prmt(zp1[m], SEL_LO);
                unsigned t2 = prmt(zp2[m], SEL_LO);
                ROW_OP(l, t0, t1, t2); l++;
                t0 = prmt(zp0[m], SEL_HI);
                t1 = prmt(zp1[m], SEL_HI);
                t2 = prmt(zp2[m], SEL_HI);
                ROW_OP(l, t0, t1, t2); l++;
            }
        }

        // Quadratic rows 17..152
        {
            int l = 1 + LATENT;
            for (int i = 0; i < LATENT; i++) {
                unsigned sel = (i & 1) ? SEL_HI : SEL_LO;
                unsigned zi0 = prmt(zp0[i >> 1], sel);
                unsigned zi1 = prmt(zp1[i >> 1], sel);
                unsigned zi2 = prmt(zp2[i >> 1], sel);
                int m = i >> 1;
                {
                    unsigned pp0 = hmul2(zi0, zp0[m]);
                    unsigned pp1 = hmul2(zi1, zp1[m]);
                    unsigned pp2 = hmul2(zi2, zp2[m]);
                    if (!(i & 1)) {
                        ROW_OP(l, prmt(pp0, SEL_LO), prmt(pp1, SEL_LO), prmt(pp2, SEL_LO));
                        l++;
                    }
                    ROW_OP(l, prmt(pp0, SEL_HI), prmt(pp1, SEL_HI), prmt(pp2, SEL_HI));
                    l++;
                }
                for (m = (i >> 1) + 1; m < 8; m++) {
                    unsigned pp0 = hmul2(zi0, zp0[m]);
                    unsigned pp1 = hmul2(zi1, zp1[m]);
                    unsigned pp2 = hmul2(zi2, zp2[m]);
                    ROW_OP(l, prmt(pp0, SEL_LO), prmt(pp1, SEL_LO), prmt(pp2, SEL_LO));
                    l++;
                    ROW_OP(l, prmt(pp0, SEL_HI), prmt(pp1, SEL_HI), prmt(pp2, SEL_HI));
                    l++;
                }
            }
        }

        // Sine rows 153..168 (inline)
        {
            int l = 153;
            #pragma unroll 2
            for (int m = 0; m < 8; m++) {
                unsigned s0, s1, s2;
                CVT2(s0, __sinf(z0[2*m]), __sinf(z0[2*m+1]));
                CVT2(s1, __sinf(z1[2*m]), __sinf(z1[2*m+1]));
                CVT2(s2, __sinf(z2[2*m]), __sinf(z2[2*m+1]));
                ROW_OP(l, prmt(s0, SEL_LO), prmt(s1, SEL_LO), prmt(s2, SEL_LO));
                l++;
                ROW_OP(l, prmt(s0, SEL_HI), prmt(s1, SEL_HI), prmt(s2, SEL_HI));
                l++;
            }
        }
        #undef ROW_OP

        // Euler: z += dz * DT
        #pragma unroll
        for (int q = 0; q < 8; q++) {
            z0[2*q+0] = fmaf(bf16lo_f(acc0[q]), DT_F, z0[2*q+0]);
            z0[2*q+1] = fmaf(bf16hi_f(acc0[q]), DT_F, z0[2*q+1]);
            z1[2*q+0] = fmaf(bf16lo_f(acc1[q]), DT_F, z1[2*q+0]);
            z1[2*q+1] = fmaf(bf16hi_f(acc1[q]), DT_F, z1[2*q+1]);
            z2[2*q+0] = fmaf(bf16lo_f(acc2[q]), DT_F, z2[2*q+0]);
            z2[2*q+1] = fmaf(bf16hi_f(acc2[q]), DT_F, z2[2*q+1]);
        }
    }

    {
        float4* po = reinterpret_cast<float4*>(out + ((size_t)n0 * NREP + r) * LATENT);
        #pragma unroll
        for (int k = 0; k < 4; k++)
            po[k] = make_float4(z0[4*k+0], z0[4*k+1], z0[4*k+2], z0[4*k+3]);
        if (v1) {
            float4* p1 = reinterpret_cast<float4*>(out + ((size_t)n1 * NREP + r) * LATENT);
            #pragma unroll
            for (int k = 0; k < 4; k++)
                p1[k] = make_float4(z1[4*k+0], z1[4*k+1], z1[4*k+2], z1[4*k+3]);
        }
        if (v2) {
            float4* p2 = reinterpret_cast<float4*>(out + ((size_t)n2 * NREP + r) * LATENT);
            #pragma unroll
            for (int k = 0; k < 4; k++)
                p2[k] = make_float4(z2[4*k+0], z2[4*k+1], z2[4*k+2], z2[4*k+3]);
        }
    }
}

extern "C" void kernel_launch(void* const* d_in, const int* in_sizes, int n_in,
                              void* d_out, int out_size)
{
    const float* h_t   = (const float*)d_in[0];   // [50000, 16]
    const float* coeff = (const float*)d_in[1];   // [10, 169, 16]
    const float* mask  = (const float*)d_in[2];   // [10, 169, 16]
    float* out = (float*)d_out;                   // [50000, 10, 16]

    int n_total = in_sizes[0] / LATENT;
    int blocks_x = (n_total + 383) / 384;
    dim3 grid((unsigned)blocks_x, NREP, 1);
    sindy_shred_kernel<<<grid, 128>>>(h_t, coeff, mask, out, n_total);
}